// round 4
// baseline (speedup 1.0000x reference)
#include <cuda_runtime.h>

// STN bilinear sampler, v4.
// x: [32,256,256,32] f32 NHWC ; theta: [32,6] f32 ; out: same shape.
// One thread: EIGHT channels (2x float4) of FOUR output pixels (oy..oy+3).
// 4 threads/pixel -> per-neighbor gather still covers the full 128B input
// line per warp, but coordinate math is replicated only 4x per pixel.

#define B_ 32
#define H_ 256
#define W_ 256
#define ROWS_ 4
#define STEP (2.0f / 255.0f)

__global__ __launch_bounds__(256) void stn_kernel(
    const float4* __restrict__ xf,
    const float* __restrict__ theta,
    float4* __restrict__ out)
{
    int gid = blockIdx.x * blockDim.x + threadIdx.x;   // [0, B*(H/4)*W*4)
    int h   = gid & 3;                 // 32B sub-line: float4 pair (2h, 2h+1)
    int ox  = (gid >> 2) & 255;
    int oyq = (gid >> 10) & 63;        // quarter-row index
    int b   = gid >> 16;               // batch
    int oy  = oyq << 2;
    int cg2 = h << 1;                  // first float4 index within pixel

    // affine params (uniform per batch, L1 broadcast)
    const float* t = theta + b * 6;
    float t0 = __ldg(t + 0), t1 = __ldg(t + 1), t2 = __ldg(t + 2);
    float t3 = __ldg(t + 3), t4 = __ldg(t + 4), t5 = __ldg(t + 5);

    float gx = -1.0f + (float)ox * STEP;
    int basep = b << 16;               // b * H*W
    int obase = ((basep + (oy << 8) + ox) << 3) + cg2;

#pragma unroll
    for (int k = 0; k < ROWS_; k++) {
        float gy = -1.0f + (float)(oy + k) * STEP;

        // identical formula to reference: 0.5*(T·g + 1)*N, truncate toward zero
        float sx = 0.5f * (t0 * gx + t1 * gy + t2 + 1.0f) * (float)W_;
        float sy = 0.5f * (t3 * gx + t4 * gy + t5 + 1.0f) * (float)H_;

        int x0 = (int)sx;
        int y0 = (int)sy;

        int x0c = min(max(x0, 0), W_ - 1);
        int x1c = min(max(x0 + 1, 0), W_ - 1);
        int y0c = min(max(y0, 0), H_ - 1);
        int y1c = min(max(y0 + 1, 0), H_ - 1);

        float x0f = (float)x0c, x1f = (float)x1c;
        float y0f = (float)y0c, y1f = (float)y1c;

        float wa = (x1f - sx) * (y1f - sy);
        float wb = (x1f - sx) * (sy - y0f);
        float wc = (sx - x0f) * (y1f - sy);
        float wd = (sx - x0f) * (sy - y0f);

        // float4-unit indices; x1 column derived via dx (0 or 8)
        int dx = (x1c - x0c) << 3;
        int ia = ((basep + (y0c << 8) + x0c) << 3) + cg2;
        int ib = ((basep + (y1c << 8) + x0c) << 3) + cg2;

        // 8 independent LDG.128 -> high MLP
        float4 pa0 = __ldg(xf + ia);
        float4 pa1 = __ldg(xf + ia + 1);
        float4 pc0 = __ldg(xf + ia + dx);
        float4 pc1 = __ldg(xf + ia + dx + 1);
        float4 pb0 = __ldg(xf + ib);
        float4 pb1 = __ldg(xf + ib + 1);
        float4 pd0 = __ldg(xf + ib + dx);
        float4 pd1 = __ldg(xf + ib + dx + 1);

        float4 o0, o1;
        o0.x = wa * pa0.x + wb * pb0.x + wc * pc0.x + wd * pd0.x;
        o0.y = wa * pa0.y + wb * pb0.y + wc * pc0.y + wd * pd0.y;
        o0.z = wa * pa0.z + wb * pb0.z + wc * pc0.z + wd * pd0.z;
        o0.w = wa * pa0.w + wb * pb0.w + wc * pc0.w + wd * pd0.w;
        o1.x = wa * pa1.x + wb * pb1.x + wc * pc1.x + wd * pd1.x;
        o1.y = wa * pa1.y + wb * pb1.y + wc * pc1.y + wd * pd1.y;
        o1.z = wa * pa1.z + wb * pb1.z + wc * pc1.z + wd * pd1.z;
        o1.w = wa * pa1.w + wb * pb1.w + wc * pc1.w + wd * pd1.w;

        // streaming stores: output is write-once, keep L2 for the gather set
        __stcs(out + obase + (k << 11), o0);      // k * W_ * 8
        __stcs(out + obase + (k << 11) + 1, o1);
    }
}

extern "C" void kernel_launch(void* const* d_in, const int* in_sizes, int n_in,
                              void* d_out, int out_size)
{
    const float4* x    = (const float4*)d_in[0];
    const float* theta = (const float*)d_in[1];
    float4* out = (float4*)d_out;

    int total_threads = B_ * (H_ / ROWS_) * W_ * 4;   // 2,097,152
    int block = 256;
    int grid = total_threads / block;                  // 8,192
    stn_kernel<<<grid, block>>>(x, theta, out);
}

// round 5
// speedup vs baseline: 1.3141x; 1.3141x over previous
#include <cuda_runtime.h>

// STN bilinear sampler, v5.
// x: [32,256,256,32] f32 NHWC ; theta: [32,6] f32 ; out: same shape.
// Layout (wavefront-optimal, from v3): 8 threads/pixel, one float4 each ->
// each gather LDG.128 covers exactly 4 distinct 128B input lines per warp.
// One thread covers EIGHT output rows; depth-2 software pipeline keeps 8
// LDG.128 in flight per thread to cover long-scoreboard latency.

#define B_ 32
#define H_ 256
#define W_ 256
#define ROWS_ 8
#define STEP (2.0f / 255.0f)

struct Samp {
    float wa, wb, wc, wd;
    int ia, ib, dx;
};

__device__ __forceinline__ Samp make_samp(
    float gx, float gy,
    float t0, float t1, float t2, float t3, float t4, float t5,
    int basep, int cg)
{
    // identical formula to reference: 0.5*(T·g + 1)*N, truncate toward zero
    float sx = 0.5f * (t0 * gx + t1 * gy + t2 + 1.0f) * (float)W_;
    float sy = 0.5f * (t3 * gx + t4 * gy + t5 + 1.0f) * (float)H_;

    int x0 = (int)sx;
    int y0 = (int)sy;

    int x0c = min(max(x0, 0), W_ - 1);
    int x1c = min(max(x0 + 1, 0), W_ - 1);
    int y0c = min(max(y0, 0), H_ - 1);
    int y1c = min(max(y0 + 1, 0), H_ - 1);

    float x0f = (float)x0c, x1f = (float)x1c;
    float y0f = (float)y0c, y1f = (float)y1c;

    Samp s;
    s.wa = (x1f - sx) * (y1f - sy);
    s.wb = (x1f - sx) * (sy - y0f);
    s.wc = (sx - x0f) * (y1f - sy);
    s.wd = (sx - x0f) * (sy - y0f);
    s.dx = (x1c - x0c) << 3;
    s.ia = ((basep + (y0c << 8) + x0c) << 3) + cg;
    s.ib = ((basep + (y1c << 8) + x0c) << 3) + cg;
    return s;
}

__global__ __launch_bounds__(256) void stn_kernel(
    const float4* __restrict__ xf,
    const float* __restrict__ theta,
    float4* __restrict__ out)
{
    int gid = blockIdx.x * blockDim.x + threadIdx.x;   // [0, B*(H/8)*W*8)
    int cg  = gid & 7;                 // channel group (float4 within pixel)
    int ox  = (gid >> 3) & 255;
    int oy8 = (gid >> 11) & 31;        // 8-row group index
    int b   = gid >> 16;               // batch
    int oy  = oy8 << 3;

    // affine params (uniform per batch, L1 broadcast) — amortized over 8 rows
    const float* t = theta + b * 6;
    float t0 = __ldg(t + 0), t1 = __ldg(t + 1), t2 = __ldg(t + 2);
    float t3 = __ldg(t + 3), t4 = __ldg(t + 4), t5 = __ldg(t + 5);

    float gx = -1.0f + (float)ox * STEP;
    int basep = b << 16;               // b * H*W
    int obase = ((basep + (oy << 8) + ox) << 3) + cg;

    // ---- depth-2 software pipeline ----
    Samp s[2];
    float4 pa[2], pb[2], pc[2], pd[2];

    {
        float gy0 = -1.0f + (float)oy * STEP;
        s[0] = make_samp(gx, gy0, t0, t1, t2, t3, t4, t5, basep, cg);
        pa[0] = __ldg(xf + s[0].ia);
        pc[0] = __ldg(xf + s[0].ia + s[0].dx);
        pb[0] = __ldg(xf + s[0].ib);
        pd[0] = __ldg(xf + s[0].ib + s[0].dx);
    }

#pragma unroll
    for (int k = 0; k < ROWS_; k++) {
        int cur = k & 1, nxt = cur ^ 1;

        if (k < ROWS_ - 1) {
            float gy = -1.0f + (float)(oy + k + 1) * STEP;
            s[nxt] = make_samp(gx, gy, t0, t1, t2, t3, t4, t5, basep, cg);
            pa[nxt] = __ldg(xf + s[nxt].ia);
            pc[nxt] = __ldg(xf + s[nxt].ia + s[nxt].dx);
            pb[nxt] = __ldg(xf + s[nxt].ib);
            pd[nxt] = __ldg(xf + s[nxt].ib + s[nxt].dx);
        }

        float4 o;
        o.x = s[cur].wa * pa[cur].x + s[cur].wb * pb[cur].x
            + s[cur].wc * pc[cur].x + s[cur].wd * pd[cur].x;
        o.y = s[cur].wa * pa[cur].y + s[cur].wb * pb[cur].y
            + s[cur].wc * pc[cur].y + s[cur].wd * pd[cur].y;
        o.z = s[cur].wa * pa[cur].z + s[cur].wb * pb[cur].z
            + s[cur].wc * pc[cur].z + s[cur].wd * pd[cur].z;
        o.w = s[cur].wa * pa[cur].w + s[cur].wb * pb[cur].w
            + s[cur].wc * pc[cur].w + s[cur].wd * pd[cur].w;

        // streaming store: output is write-once, keep L2 for the gather set
        __stcs(out + obase + (k << 11), o);   // k * W_ * 8
    }
}

extern "C" void kernel_launch(void* const* d_in, const int* in_sizes, int n_in,
                              void* d_out, int out_size)
{
    const float4* x    = (const float4*)d_in[0];
    const float* theta = (const float*)d_in[1];
    float4* out = (float4*)d_out;

    int total_threads = B_ * (H_ / ROWS_) * W_ * 8;   // 2,097,152
    int block = 256;
    int grid = total_threads / block;                  // 8,192
    stn_kernel<<<grid, block>>>(x, theta, out);
}